// round 1
// baseline (speedup 1.0000x reference)
#include <cuda_runtime.h>

#define Bq 2
#define Nq 8192
#define Mq 8192
#define Dq 64
#define TN 64
#define TM 64
#define S  67   // odd smem stride -> conflict-free scalar LDS patterns

// Scratch for precomputed row norms (allocation-free rule: __device__ globals)
__device__ float g_sqp[Bq * Nq];
__device__ float g_sqr[Bq * Mq];

// One warp per row: sum of squares over D=64
__global__ void row_norm_kernel(const float* __restrict__ x, int rows, int which)
{
    float* outp = which ? g_sqr : g_sqp;
    int warp = (blockIdx.x * blockDim.x + threadIdx.x) >> 5;
    int lane = threadIdx.x & 31;
    if (warp >= rows) return;
    const float* p = x + (size_t)warp * Dq;
    float v0 = p[lane];
    float v1 = p[lane + 32];
    float s = v0 * v0 + v1 * v1;
    #pragma unroll
    for (int o = 16; o; o >>= 1) s += __shfl_xor_sync(0xffffffffu, s, o);
    if (lane == 0) outp[warp] = s;
}

__global__ __launch_bounds__(256) void meanshift_kernel(
    const float* __restrict__ points,
    const float* __restrict__ refp,
    float* __restrict__ out)
{
    extern __shared__ float sm[];
    float* pts_s = sm;                 // [TN][S]
    float* ref_s = sm + TN * S;        // [TM][S]
    float* kt_s  = sm + 2 * TN * S;    // [TN][S]
    float* sqp_s = sm + 3 * TN * S;    // [TN]
    float* sqr_s = sqp_s + TN;         // [TM]
    float* den_s = sqr_s + TM;         // [TN]

    const int b  = blockIdx.y;
    const int n0 = blockIdx.x * TN;
    const int t  = threadIdx.x;
    const int tx = t & 15;             // 16 cols/dims groups
    const int ty = t >> 4;             // 16 row groups

    const float* Pb = points + ((size_t)b * Nq + n0) * Dq;
    const float* Rb = refp + (size_t)b * Mq * Dq;

    // Load points tile [TN][D] (coalesced), row-major stride S
    #pragma unroll
    for (int i = 0; i < 16; i++) {
        int idx = t + 256 * i;         // 0..4095
        int r = idx >> 6, d = idx & 63;
        pts_s[r * S + d] = Pb[idx];
    }
    if (t < TN) sqp_s[t] = g_sqp[b * Nq + n0 + t];

    float nacc[4][4];
    float dacc[4];
    #pragma unroll
    for (int i = 0; i < 4; i++) {
        dacc[i] = 0.f;
        #pragma unroll
        for (int j = 0; j < 4; j++) nacc[i][j] = 0.f;
    }

    for (int m0 = 0; m0 < Mq; m0 += TM) {
        __syncthreads();  // previous phase-3 done reading ref_s
        // Load ref tile [TM][D]
        #pragma unroll
        for (int i = 0; i < 16; i++) {
            int idx = t + 256 * i;
            int r = idx >> 6, d = idx & 63;
            ref_s[r * S + d] = Rb[(size_t)m0 * Dq + idx];
        }
        if (t < TM) sqr_s[t] = g_sqr[b * Mq + m0 + t];
        __syncthreads();

        // Phase 2: k tile = exp(-(sqp + sqr - 2*dot)/128)
        float acc[4][4];
        #pragma unroll
        for (int i = 0; i < 4; i++)
            #pragma unroll
            for (int j = 0; j < 4; j++) acc[i][j] = 0.f;

        #pragma unroll 4
        for (int k = 0; k < Dq; k++) {
            float a[4], bb[4];
            #pragma unroll
            for (int i = 0; i < 4; i++) a[i] = pts_s[(ty + 16 * i) * S + k];
            #pragma unroll
            for (int j = 0; j < 4; j++) bb[j] = ref_s[(tx + 16 * j) * S + k];
            #pragma unroll
            for (int i = 0; i < 4; i++)
                #pragma unroll
                for (int j = 0; j < 4; j++)
                    acc[i][j] += a[i] * bb[j];
        }
        #pragma unroll
        for (int i = 0; i < 4; i++) {
            float sp = sqp_s[ty + 16 * i];
            #pragma unroll
            for (int j = 0; j < 4; j++) {
                float sij = sp + sqr_s[tx + 16 * j] - 2.f * acc[i][j];
                kt_s[(ty + 16 * i) * S + (tx + 16 * j)] = __expf(sij * -0.0078125f);
            }
        }
        __syncthreads();

        // Phase 3: nominator += kt @ ref ; denominator from tx==0 lanes
        #pragma unroll 4
        for (int k = 0; k < TM; k++) {
            float a[4], bb[4];
            #pragma unroll
            for (int i = 0; i < 4; i++) a[i] = kt_s[(ty + 16 * i) * S + k];
            #pragma unroll
            for (int j = 0; j < 4; j++) bb[j] = ref_s[k * S + (tx + 16 * j)];
            #pragma unroll
            for (int i = 0; i < 4; i++)
                #pragma unroll
                for (int j = 0; j < 4; j++)
                    nacc[i][j] += a[i] * bb[j];
            if (tx == 0) {
                #pragma unroll
                for (int i = 0; i < 4; i++) dacc[i] += a[i];
            }
        }
    }

    if (tx == 0) {
        #pragma unroll
        for (int i = 0; i < 4; i++) den_s[ty + 16 * i] = dacc[i];
    }
    __syncthreads();

    float* Ob = out + ((size_t)b * Nq + n0) * Dq;
    #pragma unroll
    for (int i = 0; i < 4; i++) {
        int r = ty + 16 * i;
        float inv = 1.f / den_s[r];
        #pragma unroll
        for (int j = 0; j < 4; j++)
            Ob[r * Dq + tx + 16 * j] = nacc[i][j] * inv;
    }
}

extern "C" void kernel_launch(void* const* d_in, const int* in_sizes, int n_in,
                              void* d_out, int out_size)
{
    const float* points = (const float*)d_in[0];
    const float* refp   = (const float*)d_in[1];
    float* out          = (float*)d_out;

    // Row norms: one warp per row, 8 warps/block
    {
        int rows = Bq * Nq;
        int blocks = (rows * 32 + 255) / 256;
        row_norm_kernel<<<blocks, 256>>>(points, rows, 0);
    }
    {
        int rows = Bq * Mq;
        int blocks = (rows * 32 + 255) / 256;
        row_norm_kernel<<<blocks, 256>>>(refp, rows, 1);
    }

    const int smem_bytes = (3 * TN * S + 3 * TN) * (int)sizeof(float);
    static int attr_set = 0;
    if (!attr_set) {
        cudaFuncSetAttribute(meanshift_kernel,
                             cudaFuncAttributeMaxDynamicSharedMemorySize, smem_bytes);
        attr_set = 1;
    }
    dim3 grid(Nq / TN, Bq);
    meanshift_kernel<<<grid, 256, smem_bytes>>>(points, refp, out);
}

// round 4
// speedup vs baseline: 4.4913x; 4.4913x over previous
#include <cuda_runtime.h>
#include <cstdint>

typedef unsigned int u32;

#define Nq 8192
#define Mq 8192
#define Dq 64
#define TNr 128
#define NCHUNK 64

#define SR 68    // P/R row stride (floats): 68 % 32 == 4 -> conflict-free frag LDS
#define SK 132   // K row stride (floats): 132 % 32 == 4

#define C1F (1.0f/(128.0f*0.69314718055994531f))
#define C2F (2.0f*C1F)

// SMEM float offsets
#define OFF_P   0
#define OFF_R   (OFF_P + 128*SR)            // 2 buffers
#define OFF_K   (OFF_R + 2*128*SR)
#define OFF_SQP (OFF_K + 128*SK)
#define OFF_SQR (OFF_SQP + 128)             // 2 x 128
#define OFF_DEN (OFF_SQR + 256)             // 2 x 128
#define SMEM_F  (OFF_DEN + 256)

__device__ __forceinline__ void mma_tf32(float c[4], u32 a0, u32 a1, u32 a2, u32 a3,
                                         u32 b0, u32 b1)
{
    asm volatile(
        "mma.sync.aligned.m16n8k8.row.col.f32.tf32.tf32.f32 "
        "{%0,%1,%2,%3}, {%4,%5,%6,%7}, {%8,%9}, {%0,%1,%2,%3};"
        : "+f"(c[0]), "+f"(c[1]), "+f"(c[2]), "+f"(c[3])
        : "r"(a0), "r"(a1), "r"(a2), "r"(a3), "r"(b0), "r"(b1));
}
__device__ __forceinline__ float ex2(float x){
    float r; asm("ex2.approx.ftz.f32 %0, %1;" : "=f"(r) : "f"(x)); return r;
}
__device__ __forceinline__ float rcpf(float x){
    float r; asm("rcp.approx.ftz.f32 %0, %1;" : "=f"(r) : "f"(x)); return r;
}
// Round fp32 to tf32 (RNA = round to nearest) -> fp32 container with low 13 bits zero
__device__ __forceinline__ float rtf(float x){
    u32 r; asm("cvt.rna.tf32.f32 %0, %1;" : "=r"(r) : "f"(x));
    return __uint_as_float(r);
}
__device__ __forceinline__ void cpasync16(u32 dst, const void* src){
    asm volatile("cp.async.cg.shared.global [%0], [%1], 16;" :: "r"(dst), "l"(src));
}
__device__ __forceinline__ u32 fbits(float x){ return __float_as_uint(x); }

__global__ void __launch_bounds__(256, 1) ms_kernel(
    const float* __restrict__ P, const float* __restrict__ Rf, float* __restrict__ out)
{
    extern __shared__ float sm[];
    float* Ps   = sm + OFF_P;
    float* Rs0  = sm + OFF_R;
    float* Ks   = sm + OFF_K;
    float* sqp  = sm + OFF_SQP;
    float* sqr0 = sm + OFF_SQR;
    float* denp = sm + OFF_DEN;

    const int t = threadIdx.x;
    const int w = t >> 5, l = t & 31;
    const int gid = l >> 2, tig = l & 3;       // groupID, threadID-in-group
    const int b = blockIdx.y;
    const int n0 = blockIdx.x * TNr;
    const float* Pb = P + ((size_t)b * Nq + n0) * Dq;
    const float* Rb = Rf + (size_t)b * Mq * Dq;

    // GEMM1 warp grid 4x2 (32m x 64n), GEMM2 warp grid 4x2 (32m x 32n)
    const int wm = (w & 3) * 32;
    const int wn1 = (w >> 2) * 64;
    const int wn2 = (w >> 2) * 32;

    // ---- Prologue: cp.async R chunk 0; direct-load P (tf32-rounded) + row norms ----
    {
        const float4* g4 = (const float4*)Rb;
        #pragma unroll
        for (int it = 0; it < 8; it++){
            int idx = t + (it << 8);
            int r = idx >> 4, c4 = idx & 15;
            u32 dst = (u32)__cvta_generic_to_shared(&Rs0[r * SR + c4 * 4]);
            cpasync16(dst, g4 + idx);
        }
        asm volatile("cp.async.commit_group;");
    }
    {
        const float4* g4 = (const float4*)Pb;
        #pragma unroll
        for (int it = 0; it < 8; it++){
            int idx = t + (it << 8);
            int r = idx >> 4, c4 = idx & 15;
            float4 v = g4[idx];
            v.x = rtf(v.x); v.y = rtf(v.y); v.z = rtf(v.z); v.w = rtf(v.w);
            *(float4*)&Ps[r * SR + c4 * 4] = v;
            float s = v.x*v.x + v.y*v.y + v.z*v.z + v.w*v.w;
            s += __shfl_xor_sync(0xffffffffu, s, 1);
            s += __shfl_xor_sync(0xffffffffu, s, 2);
            s += __shfl_xor_sync(0xffffffffu, s, 4);
            s += __shfl_xor_sync(0xffffffffu, s, 8);
            if ((l & 15) == 0) sqp[r] = s * C1F;
        }
    }

    float nacc[2][4][4];
    float dacc[4];
    #pragma unroll
    for (int i = 0; i < 2; i++)
        #pragma unroll
        for (int j = 0; j < 4; j++)
            #pragma unroll
            for (int q = 0; q < 4; q++) nacc[i][j][q] = 0.f;
    #pragma unroll
    for (int i = 0; i < 4; i++) dacc[i] = 0.f;

    for (int i = 0; i < NCHUNK; i++){
        const int p = i & 1;
        float* Rs  = Rs0 + p * 128 * SR;
        float* sqr = sqr0 + p * 128;

        asm volatile("cp.async.wait_group 0;" ::: "memory");
        __syncthreads();

        if (i + 1 < NCHUNK){
            float* Rn = Rs0 + (p ^ 1) * 128 * SR;
            const float4* g4 = (const float4*)(Rb + (size_t)(i + 1) * 128 * Dq);
            #pragma unroll
            for (int it = 0; it < 8; it++){
                int idx = t + (it << 8);
                int r = idx >> 4, c4 = idx & 15;
                u32 dst = (u32)__cvta_generic_to_shared(&Rn[r * SR + c4 * 4]);
                cpasync16(dst, g4 + idx);
            }
            asm volatile("cp.async.commit_group;");
        }

        // R pass: round to tf32 in place + row norms (from rounded values)
        {
            int r = t >> 1, h = t & 1;
            float4* row = (float4*)&Rs[r * SR + h * 32];
            float s = 0.f;
            #pragma unroll
            for (int j = 0; j < 8; j++){
                float4 v = row[j];
                v.x = rtf(v.x); v.y = rtf(v.y); v.z = rtf(v.z); v.w = rtf(v.w);
                row[j] = v;
                s += v.x*v.x + v.y*v.y + v.z*v.z + v.w*v.w;
            }
            s += __shfl_xor_sync(0xffffffffu, s, 1);
            if (h == 0) sqr[r] = s * C1F;
        }
        __syncthreads();

        // ---- GEMM1: S = P . R^T  (warp tile 32 x 64) ----
        float sa[2][8][4];
        #pragma unroll
        for (int mt = 0; mt < 2; mt++)
            #pragma unroll
            for (int nt = 0; nt < 8; nt++)
                #pragma unroll
                for (int q = 0; q < 4; q++) sa[mt][nt][q] = 0.f;

        #pragma unroll
        for (int ks = 0; ks < 8; ks++){
            u32 a[2][4];
            #pragma unroll
            for (int mt = 0; mt < 2; mt++){
                const float* pa = &Ps[(wm + 16*mt + gid) * SR + ks*8 + tig];
                a[mt][0] = fbits(pa[0]);
                a[mt][1] = fbits(pa[8*SR]);
                a[mt][2] = fbits(pa[4]);
                a[mt][3] = fbits(pa[8*SR + 4]);
            }
            #pragma unroll
            for (int nt = 0; nt < 8; nt++){
                const float* pb = &Rs[(wn1 + 8*nt + gid) * SR + ks*8 + tig];
                u32 b0 = fbits(pb[0]), b1 = fbits(pb[4]);
                #pragma unroll
                for (int mt = 0; mt < 2; mt++)
                    mma_tf32(sa[mt][nt], a[mt][0], a[mt][1], a[mt][2], a[mt][3], b0, b1);
            }
        }

        // ---- Epilogue: K = exp2(C2*S - C1|p|^2 - C1|r|^2), tf32-rounded; den from rounded ----
        #pragma unroll
        for (int mt = 0; mt < 2; mt++){
            int r0 = wm + 16*mt + gid;
            float spa0 = sqp[r0];
            float spa1 = sqp[r0 + 8];
            #pragma unroll
            for (int nt = 0; nt < 8; nt++){
                int c0 = wn1 + 8*nt + 2*tig;
                float2 q = *(const float2*)&sqr[c0];
                float e0 = rtf(ex2(fmaf(C2F, sa[mt][nt][0], -spa0 - q.x)));
                float e1 = rtf(ex2(fmaf(C2F, sa[mt][nt][1], -spa0 - q.y)));
                float e2 = rtf(ex2(fmaf(C2F, sa[mt][nt][2], -spa1 - q.x)));
                float e3 = rtf(ex2(fmaf(C2F, sa[mt][nt][3], -spa1 - q.y)));
                dacc[2*mt + 0] += e0 + e1;
                dacc[2*mt + 1] += e2 + e3;
                *(float2*)&Ks[r0 * SK + c0]       = make_float2(e0, e1);
                *(float2*)&Ks[(r0 + 8) * SK + c0] = make_float2(e2, e3);
            }
        }
        __syncthreads();

        // ---- GEMM2: num += K . R  (warp tile 32 x 32, k = 128) ----
        #pragma unroll
        for (int ks = 0; ks < 16; ks++){
            u32 a[2][4];
            #pragma unroll
            for (int mt = 0; mt < 2; mt++){
                const float* pa = &Ks[(wm + 16*mt + gid) * SK + ks*8 + tig];
                a[mt][0] = fbits(pa[0]);
                a[mt][1] = fbits(pa[8*SK]);
                a[mt][2] = fbits(pa[4]);
                a[mt][3] = fbits(pa[8*SK + 4]);
            }
            #pragma unroll
            for (int nt = 0; nt < 4; nt++){
                const float* pb = &Rs[(ks*8 + tig) * SR + wn2 + 8*nt + gid];
                u32 b0 = fbits(pb[0]);
                u32 b1 = fbits(pb[4*SR]);
                #pragma unroll
                for (int mt = 0; mt < 2; mt++)
                    mma_tf32(nacc[mt][nt], a[mt][0], a[mt][1], a[mt][2], a[mt][3], b0, b1);
            }
        }
    }

    // ---- Denominator: reduce over col-lanes, publish partials ----
    #pragma unroll
    for (int d = 0; d < 4; d++){
        dacc[d] += __shfl_xor_sync(0xffffffffu, dacc[d], 1);
        dacc[d] += __shfl_xor_sync(0xffffffffu, dacc[d], 2);
    }
    if (tig == 0){
        #pragma unroll
        for (int mt = 0; mt < 2; mt++){
            denp[(w >> 2) * 128 + wm + 16*mt + gid]     = dacc[2*mt + 0];
            denp[(w >> 2) * 128 + wm + 16*mt + 8 + gid] = dacc[2*mt + 1];
        }
    }
    __syncthreads();

    // ---- Stage num to smem (reuse K buffer, stride SR) ----
    #pragma unroll
    for (int mt = 0; mt < 2; mt++){
        int r0 = wm + 16*mt + gid;
        #pragma unroll
        for (int nt = 0; nt < 4; nt++){
            int c0 = wn2 + 8*nt + 2*tig;
            *(float2*)&Ks[r0 * SR + c0]       = make_float2(nacc[mt][nt][0], nacc[mt][nt][1]);
            *(float2*)&Ks[(r0 + 8) * SR + c0] = make_float2(nacc[mt][nt][2], nacc[mt][nt][3]);
        }
    }
    __syncthreads();

    // ---- Coalesced writeback: out = num / den ----
    float4* Ob = (float4*)(out + ((size_t)b * Nq + n0) * Dq);
    #pragma unroll
    for (int it = 0; it < 8; it++){
        int idx = t + (it << 8);
        int r = idx >> 4, c4 = idx & 15;
        float4 v = *(const float4*)&Ks[r * SR + c4 * 4];
        float inv = rcpf(denp[r] + denp[128 + r]);
        v.x *= inv; v.y *= inv; v.z *= inv; v.w *= inv;
        Ob[idx] = v;
    }
}

extern "C" void kernel_launch(void* const* d_in, const int* in_sizes, int n_in,
                              void* d_out, int out_size)
{
    const float* points = (const float*)d_in[0];
    const float* refp   = (const float*)d_in[1];
    float* out          = (float*)d_out;

    const int smem_bytes = SMEM_F * (int)sizeof(float);
    static int attr_set = 0;
    if (!attr_set){
        cudaFuncSetAttribute(ms_kernel,
                             cudaFuncAttributeMaxDynamicSharedMemorySize, smem_bytes);
        attr_set = 1;
    }
    dim3 grid(Nq / TNr, 2);
    ms_kernel<<<grid, 256, smem_bytes>>>(points, refp, out);
}

// round 5
// speedup vs baseline: 5.7955x; 1.2904x over previous
#include <cuda_runtime.h>
#include <cstdint>

typedef unsigned int u32;

#define Nq 8192
#define Mq 8192
#define Dq 64
#define TNr 128
#define NCHUNK 64

#define SR 68    // row stride (floats): 68 % 32 == 4 -> conflict-free frag patterns

#define C1F (1.0f/(128.0f*0.69314718055994531f))
#define C2F (2.0f*C1F)

// SMEM float offsets
#define OFF_P   0
#define OFF_R   (OFF_P + 128*SR)            // 2 buffers
#define OFF_NUM (OFF_R + 2*128*SR)          // 128 x SR num staging
#define OFF_SQP (OFF_NUM + 128*SR)
#define OFF_SQR (OFF_SQP + 128)             // 2 x 128
#define OFF_DEN (OFF_SQR + 256)             // 2 x 128
#define SMEM_F  (OFF_DEN + 256)

__device__ __forceinline__ void mma_tf32(float c[4], u32 a0, u32 a1, u32 a2, u32 a3,
                                         u32 b0, u32 b1)
{
    asm volatile(
        "mma.sync.aligned.m16n8k8.row.col.f32.tf32.tf32.f32 "
        "{%0,%1,%2,%3}, {%4,%5,%6,%7}, {%8,%9}, {%0,%1,%2,%3};"
        : "+f"(c[0]), "+f"(c[1]), "+f"(c[2]), "+f"(c[3])
        : "r"(a0), "r"(a1), "r"(a2), "r"(a3), "r"(b0), "r"(b1));
}
__device__ __forceinline__ float ex2(float x){
    float r; asm("ex2.approx.ftz.f32 %0, %1;" : "=f"(r) : "f"(x)); return r;
}
__device__ __forceinline__ float rcpf(float x){
    float r; asm("rcp.approx.ftz.f32 %0, %1;" : "=f"(r) : "f"(x)); return r;
}
// Round fp32 -> tf32 (round-to-nearest), fp32 container
__device__ __forceinline__ float rtf(float x){
    u32 r; asm("cvt.rna.tf32.f32 %0, %1;" : "=r"(r) : "f"(x));
    return __uint_as_float(r);
}
__device__ __forceinline__ void cpasync16(u32 dst, const void* src){
    asm volatile("cp.async.cg.shared.global [%0], [%1], 16;" :: "r"(dst), "l"(src));
}
__device__ __forceinline__ u32 fbits(float x){ return __float_as_uint(x); }

__global__ void __launch_bounds__(256, 1) ms_kernel(
    const float* __restrict__ P, const float* __restrict__ Rf, float* __restrict__ out)
{
    extern __shared__ float sm[];
    float* Ps   = sm + OFF_P;
    float* Rs0  = sm + OFF_R;
    float* numb = sm + OFF_NUM;
    float* sqp  = sm + OFF_SQP;
    float* sqr0 = sm + OFF_SQR;
    float* denp = sm + OFF_DEN;

    const int t = threadIdx.x;
    const int w = t >> 5, l = t & 31;
    const int gid = l >> 2, tig = l & 3;       // groupID, threadID-in-group
    const int b = blockIdx.y;
    const int n0 = blockIdx.x * TNr;
    const float* Pb = P + ((size_t)b * Nq + n0) * Dq;
    const float* Rb = Rf + (size_t)b * Mq * Dq;

    // Warp grid 4m x 2half: wm rows, half selects the 64-col GEMM1 slice
    // (= this warp's private k-half for GEMM2).
    const int wm = (w & 3) * 32;
    const int half = w >> 2;
    const int wn1 = half * 64;

    // ---- Prologue: cp.async R chunk 0; direct-load P (tf32-rounded) + row norms ----
    {
        const float4* g4 = (const float4*)Rb;
        #pragma unroll
        for (int it = 0; it < 8; it++){
            int idx = t + (it << 8);
            int r = idx >> 4, c4 = idx & 15;
            u32 dst = (u32)__cvta_generic_to_shared(&Rs0[r * SR + c4 * 4]);
            cpasync16(dst, g4 + idx);
        }
        asm volatile("cp.async.commit_group;");
    }
    {
        const float4* g4 = (const float4*)Pb;
        #pragma unroll
        for (int it = 0; it < 8; it++){
            int idx = t + (it << 8);
            int r = idx >> 4, c4 = idx & 15;
            float4 v = g4[idx];
            v.x = rtf(v.x); v.y = rtf(v.y); v.z = rtf(v.z); v.w = rtf(v.w);
            *(float4*)&Ps[r * SR + c4 * 4] = v;
            float s = v.x*v.x + v.y*v.y + v.z*v.z + v.w*v.w;
            s += __shfl_xor_sync(0xffffffffu, s, 1);
            s += __shfl_xor_sync(0xffffffffu, s, 2);
            s += __shfl_xor_sync(0xffffffffu, s, 4);
            s += __shfl_xor_sync(0xffffffffu, s, 8);
            if ((l & 15) == 0) sqp[r] = s * C1F;
        }
    }

    // Partial numerator over this warp's k-half: 32m x 64n
    float nacc[2][8][4];
    float dacc[4];
    #pragma unroll
    for (int i = 0; i < 2; i++)
        #pragma unroll
        for (int j = 0; j < 8; j++)
            #pragma unroll
            for (int q = 0; q < 4; q++) nacc[i][j][q] = 0.f;
    #pragma unroll
    for (int i = 0; i < 4; i++) dacc[i] = 0.f;

    for (int i = 0; i < NCHUNK; i++){
        const int p = i & 1;
        float* Rs  = Rs0 + p * 128 * SR;
        float* sqr = sqr0 + p * 128;

        asm volatile("cp.async.wait_group 0;" ::: "memory");
        __syncthreads();

        if (i + 1 < NCHUNK){
            float* Rn = Rs0 + (p ^ 1) * 128 * SR;
            const float4* g4 = (const float4*)(Rb + (size_t)(i + 1) * 128 * Dq);
            #pragma unroll
            for (int it = 0; it < 8; it++){
                int idx = t + (it << 8);
                int r = idx >> 4, c4 = idx & 15;
                u32 dst = (u32)__cvta_generic_to_shared(&Rn[r * SR + c4 * 4]);
                cpasync16(dst, g4 + idx);
            }
            asm volatile("cp.async.commit_group;");
        }

        // R pass: round to tf32 in place + row norms (from rounded values)
        {
            int r = t >> 1, h = t & 1;
            float4* row = (float4*)&Rs[r * SR + h * 32];
            float s = 0.f;
            #pragma unroll
            for (int j = 0; j < 8; j++){
                float4 v = row[j];
                v.x = rtf(v.x); v.y = rtf(v.y); v.z = rtf(v.z); v.w = rtf(v.w);
                row[j] = v;
                s += v.x*v.x + v.y*v.y + v.z*v.z + v.w*v.w;
            }
            s += __shfl_xor_sync(0xffffffffu, s, 1);
            if (h == 0) sqr[r] = s * C1F;
        }
        __syncthreads();

        // ---- GEMM1: S = P . R^T  (warp tile 32 x 64) ----
        float sa[2][8][4];
        #pragma unroll
        for (int mt = 0; mt < 2; mt++)
            #pragma unroll
            for (int nt = 0; nt < 8; nt++)
                #pragma unroll
                for (int q = 0; q < 4; q++) sa[mt][nt][q] = 0.f;

        #pragma unroll
        for (int ks = 0; ks < 8; ks++){
            u32 a[2][4];
            #pragma unroll
            for (int mt = 0; mt < 2; mt++){
                const float* pa = &Ps[(wm + 16*mt + gid) * SR + ks*8 + tig];
                a[mt][0] = fbits(pa[0]);
                a[mt][1] = fbits(pa[8*SR]);
                a[mt][2] = fbits(pa[4]);
                a[mt][3] = fbits(pa[8*SR + 4]);
            }
            #pragma unroll
            for (int nt = 0; nt < 8; nt++){
                const float* pb = &Rs[(wn1 + 8*nt + gid) * SR + ks*8 + tig];
                u32 b0 = fbits(pb[0]), b1 = fbits(pb[4]);
                #pragma unroll
                for (int mt = 0; mt < 2; mt++)
                    mma_tf32(sa[mt][nt], a[mt][0], a[mt][1], a[mt][2], a[mt][3], b0, b1);
            }
        }

        // ---- Epilogue in registers: sa <- rtf(exp2(C2*S - |p|^2 - |r|^2)); den partials ----
        #pragma unroll
        for (int mt = 0; mt < 2; mt++){
            int r0 = wm + 16*mt + gid;
            float spa0 = sqp[r0];
            float spa1 = sqp[r0 + 8];
            #pragma unroll
            for (int nt = 0; nt < 8; nt++){
                int c0 = wn1 + 8*nt + 2*tig;
                float2 q = *(const float2*)&sqr[c0];
                float e0 = rtf(ex2(fmaf(C2F, sa[mt][nt][0], -spa0 - q.x)));
                float e1 = rtf(ex2(fmaf(C2F, sa[mt][nt][1], -spa0 - q.y)));
                float e2 = rtf(ex2(fmaf(C2F, sa[mt][nt][2], -spa1 - q.x)));
                float e3 = rtf(ex2(fmaf(C2F, sa[mt][nt][3], -spa1 - q.y)));
                dacc[2*mt + 0] += e0 + e1;
                dacc[2*mt + 1] += e2 + e3;
                sa[mt][nt][0] = e0; sa[mt][nt][1] = e1;
                sa[mt][nt][2] = e2; sa[mt][nt][3] = e3;
            }
        }

        // ---- GEMM2: num_partial += K_regs . R  (k = this warp's 64 cols) ----
        // k-permutation sigma(j)=2j / 2(j-4)+1 lets C-frags feed A directly:
        // (a0,a1,a2,a3) = (c0,c2,c1,c3); B rows permuted to match.
        #pragma unroll
        for (int kt = 0; kt < 8; kt++){
            u32 a0[2], a1[2], a2[2], a3[2];
            #pragma unroll
            for (int mt = 0; mt < 2; mt++){
                a0[mt] = fbits(sa[mt][kt][0]);
                a1[mt] = fbits(sa[mt][kt][2]);
                a2[mt] = fbits(sa[mt][kt][1]);
                a3[mt] = fbits(sa[mt][kt][3]);
            }
            const float* pb = &Rs[(wn1 + 8*kt + 2*tig) * SR + gid];
            #pragma unroll
            for (int jt = 0; jt < 8; jt++){
                u32 b0 = fbits(pb[8*jt]);
                u32 b1 = fbits(pb[SR + 8*jt]);
                #pragma unroll
                for (int mt = 0; mt < 2; mt++)
                    mma_tf32(nacc[mt][jt], a0[mt], a1[mt], a2[mt], a3[mt], b0, b1);
            }
        }
    }

    // ---- Denominator: reduce over col-lanes, publish per-half partials ----
    #pragma unroll
    for (int d = 0; d < 4; d++){
        dacc[d] += __shfl_xor_sync(0xffffffffu, dacc[d], 1);
        dacc[d] += __shfl_xor_sync(0xffffffffu, dacc[d], 2);
    }
    if (tig == 0){
        #pragma unroll
        for (int mt = 0; mt < 2; mt++){
            denp[half * 128 + wm + 16*mt + gid]     = dacc[2*mt + 0];
            denp[half * 128 + wm + 16*mt + 8 + gid] = dacc[2*mt + 1];
        }
    }

    // ---- Combine the two k-half numerator partials in SMEM ----
    __syncthreads();
    if (half == 0){
        #pragma unroll
        for (int mt = 0; mt < 2; mt++){
            int r0 = wm + 16*mt + gid;
            #pragma unroll
            for (int jt = 0; jt < 8; jt++){
                int c0 = 8*jt + 2*tig;
                *(float2*)&numb[r0 * SR + c0]       = make_float2(nacc[mt][jt][0], nacc[mt][jt][1]);
                *(float2*)&numb[(r0 + 8) * SR + c0] = make_float2(nacc[mt][jt][2], nacc[mt][jt][3]);
            }
        }
    }
    __syncthreads();
    if (half == 1){
        #pragma unroll
        for (int mt = 0; mt < 2; mt++){
            int r0 = wm + 16*mt + gid;
            #pragma unroll
            for (int jt = 0; jt < 8; jt++){
                int c0 = 8*jt + 2*tig;
                float2 u0 = *(const float2*)&numb[r0 * SR + c0];
                float2 u1 = *(const float2*)&numb[(r0 + 8) * SR + c0];
                u0.x += nacc[mt][jt][0]; u0.y += nacc[mt][jt][1];
                u1.x += nacc[mt][jt][2]; u1.y += nacc[mt][jt][3];
                *(float2*)&numb[r0 * SR + c0]       = u0;
                *(float2*)&numb[(r0 + 8) * SR + c0] = u1;
            }
        }
    }
    __syncthreads();

    // ---- Coalesced writeback: out = num / den ----
    float4* Ob = (float4*)(out + ((size_t)b * Nq + n0) * Dq);
    #pragma unroll
    for (int it = 0; it < 8; it++){
        int idx = t + (it << 8);
        int r = idx >> 4, c4 = idx & 15;
        float4 v = *(const float4*)&numb[r * SR + c4 * 4];
        float inv = rcpf(denp[r] + denp[128 + r]);
        v.x *= inv; v.y *= inv; v.z *= inv; v.w *= inv;
        Ob[idx] = v;
    }
}

extern "C" void kernel_launch(void* const* d_in, const int* in_sizes, int n_in,
                              void* d_out, int out_size)
{
    const float* points = (const float*)d_in[0];
    const float* refp   = (const float*)d_in[1];
    float* out          = (float*)d_out;

    const int smem_bytes = SMEM_F * (int)sizeof(float);
    static int attr_set = 0;
    if (!attr_set){
        cudaFuncSetAttribute(ms_kernel,
                             cudaFuncAttributeMaxDynamicSharedMemorySize, smem_bytes);
        attr_set = 1;
    }
    dim3 grid(Nq / TNr, 2);
    ms_kernel<<<grid, 256, smem_bytes>>>(points, refp, out);
}